// round 14
// baseline (speedup 1.0000x reference)
#include <cuda_runtime.h>
#include <cuda_fp16.h>
#include <cstdint>
#include <math.h>

// Problem dims (fixed)
#define BB 4
#define SS 4096
#define DD 1024
#define AA 1024
#define MTOT (BB*SS)   // 16384

// ---------------------------------------------------------------------------
// Device scratch
// ---------------------------------------------------------------------------
__device__ float g_S [(size_t)BB * SS * SS];              // 256 MB scores
__device__ float g_Wt_part[4 * (size_t)DD * DD];          // 16 MB split-K partials
__device__ __half g_Xhi[(size_t)MTOT * DD];
__device__ __half g_Xlo[(size_t)MTOT * DD];
__device__ __half g_Wq16h[(size_t)DD * AA];               // 16*Wq split (row-major [D,A])
__device__ __half g_Wq16l[(size_t)DD * AA];
__device__ __half g_Wk16h[(size_t)DD * AA];
__device__ __half g_Wk16l[(size_t)DD * AA];
__device__ __half g_WvTh[(size_t)AA * DD];                // (16*Wv)^T hi [A,D]
__device__ __half g_Wth[(size_t)DD * DD];                 // 16*W~^T hi/lo [d2,d1]
__device__ __half g_Wtl[(size_t)DD * DD];
__device__ __half g_Yhi[(size_t)MTOT * DD];               // Y = X*W~ split
__device__ __half g_Ylo[(size_t)MTOT * DD];
__device__ __half g_Vthi[(size_t)BB * AA * SS];           // V^T per batch [A,S]
__device__ __half g_Phi[(size_t)BB * SS * SS];            // 128 MB

// ---------------------------------------------------------------------------
// Helpers
// ---------------------------------------------------------------------------
__device__ __forceinline__ uint32_t smem_u32(const void* p) {
    uint32_t a;
    asm("{ .reg .u64 t; cvta.to.shared.u64 t, %1; cvt.u32.u64 %0, t; }" : "=r"(a) : "l"(p));
    return a;
}

#define CP_ASYNC16(saddr, gaddr) \
    asm volatile("cp.async.cg.shared.global [%0], [%1], 16;" :: "r"(saddr), "l"(gaddr))
#define CP_COMMIT()  asm volatile("cp.async.commit_group;" ::: "memory")
#define CP_WAIT1()   asm volatile("cp.async.wait_group 1;" ::: "memory")
#define CP_WAIT0()   asm volatile("cp.async.wait_group 0;" ::: "memory")

#define MMA_F16(c, a, b) \
    asm volatile("mma.sync.aligned.m16n8k16.row.col.f32.f16.f16.f32 " \
        "{%0,%1,%2,%3}, {%4,%5,%6,%7}, {%8,%9}, {%0,%1,%2,%3};" \
        : "+f"((c)[0]), "+f"((c)[1]), "+f"((c)[2]), "+f"((c)[3]) \
        : "r"((a)[0]), "r"((a)[1]), "r"((a)[2]), "r"((a)[3]), \
          "r"((b)[0]), "r"((b)[1]))

// ---------------------------------------------------------------------------
// Persistent HMMA GEMM, fp16 hi/lo split, term count NT (f32 accumulate):
//   NT=3: AhBh + AlBh + AhBl ; NT=1: AhBh
// OUT: 0 = fp32 C; 1 = fp16 hi/lo; 2 = fp16 hi; 3 = fp16 hi transposed (V^T)
// Grid-stride over gx*gy*gz tiles; CTA tile 128x128, KC=32, 2-stage
// cp.async, 2 CTAs/SM, warp tile 32x64.
// ---------------------------------------------------------------------------
#define KC    32
#define ROWB  80                              // 32 fp16 (64B) + 16B pad
#define TILE_T (128 * ROWB)                   // 10240 B

__device__ __forceinline__ void load_tile32(const __half* __restrict__ g,
                                            int ldK, char* sb, int tid)
{
#pragma unroll
    for (int i = 0; i < 2; i++) {
        int ch = tid + i * 256;               // 0..511
        int row = ch >> 2, c = ch & 3;
        CP_ASYNC16(smem_u32(sb + row * ROWB + c * 16),
                   g + (size_t)row * ldK + c * 8);
    }
}

template <int NT>
__device__ __forceinline__ void load_stage(const __half* pAh, const __half* pAl,
                                           const __half* pBh, const __half* pBl,
                                           int k0, int ldAB, char* sp, int tid)
{
    load_tile32(pAh + k0, ldAB, sp, tid);
    if (NT == 3) {
        load_tile32(pAl + k0, ldAB, sp + TILE_T,     tid);
        load_tile32(pBh + k0, ldAB, sp + 2 * TILE_T, tid);
        load_tile32(pBl + k0, ldAB, sp + 3 * TILE_T, tid);
    } else {
        load_tile32(pBh + k0, ldAB, sp + TILE_T, tid);
    }
    CP_COMMIT();
}

template <int NT, int OUT>
__global__ __launch_bounds__(256, 2)
void gemm_mma(const __half* __restrict__ Ahi, const __half* __restrict__ Alo,
              const __half* __restrict__ Bhi, const __half* __restrict__ Blo,
              float* __restrict__ C,
              __half* __restrict__ Chi, __half* __restrict__ Clo,
              int K, int ldAB, int ldC,
              long long sA, long long sB, long long sC, float oscale,
              int gx, int gy, int gz)
{
    constexpr int STG = (NT == 3 ? 4 : 2) * TILE_T;
    extern __shared__ __align__(128) char smem[];
    const int tid = threadIdx.x;
    const int wid = tid >> 5, lane = tid & 31;
    const int wm = wid & 3, wn = wid >> 2;    // 4(m) x 2(n)
    const int r  = lane >> 2;
    const int kq = lane & 3;
    const int cq = (lane & 3) * 2;
    const int ntiles = gx * gy * gz;
    const int nch = K >> 5;

    for (int t = blockIdx.x; t < ntiles; t += gridDim.x) {
        const int bx = t % gx;
        const int by = (t / gx) % gy;
        const int bz = t / (gx * gy);
        const int m0 = by * 128;
        const int n0 = bx * 128;

        const __half* pAh = Ahi + (size_t)bz * sA + (size_t)m0 * ldAB;
        const __half* pAl = (NT == 3) ? Alo + (size_t)bz * sA + (size_t)m0 * ldAB : nullptr;
        const __half* pBh = Bhi + (size_t)bz * sB + (size_t)n0 * ldAB;
        const __half* pBl = (NT == 3) ? Blo + (size_t)bz * sB + (size_t)n0 * ldAB : nullptr;

        float acc[2][8][4];
#pragma unroll
        for (int mt = 0; mt < 2; mt++)
#pragma unroll
            for (int nt = 0; nt < 8; nt++)
#pragma unroll
                for (int j = 0; j < 4; j++) acc[mt][nt][j] = 0.0f;

        load_stage<NT>(pAh, pAl, pBh, pBl, 0,  ldAB, smem,       tid);
        load_stage<NT>(pAh, pAl, pBh, pBl, KC, ldAB, smem + STG, tid);

        for (int c = 0; c < nch; ++c) {
            if (c + 1 < nch) CP_WAIT1(); else CP_WAIT0();
            __syncthreads();

            const char* sp  = smem + (c & 1) * STG;
            const char* sAh = sp;
            const char* sAl = sp + TILE_T;                       // NT==3
            const char* sBh = sp + (NT == 3 ? 2 : 1) * TILE_T;
            const char* sBl = sp + 3 * TILE_T;                   // NT==3

#pragma unroll
            for (int ks = 0; ks < 2; ++ks) {
                const int kb = ks * 32 + kq * 4;

                uint32_t ah[2][4], al[2][4];
#pragma unroll
                for (int mt = 0; mt < 2; mt++) {
                    const int row = wm * 32 + mt * 16 + r;
                    const char* a0 = sAh + row * ROWB + kb;
                    const char* a1 = sAh + (row + 8) * ROWB + kb;
                    ah[mt][0] = *(const uint32_t*)(a0);
                    ah[mt][1] = *(const uint32_t*)(a1);
                    ah[mt][2] = *(const uint32_t*)(a0 + 16);
                    ah[mt][3] = *(const uint32_t*)(a1 + 16);
                    if (NT == 3) {
                        const char* b0 = sAl + row * ROWB + kb;
                        const char* b1 = sAl + (row + 8) * ROWB + kb;
                        al[mt][0] = *(const uint32_t*)(b0);
                        al[mt][1] = *(const uint32_t*)(b1);
                        al[mt][2] = *(const uint32_t*)(b0 + 16);
                        al[mt][3] = *(const uint32_t*)(b1 + 16);
                    }
                }
#pragma unroll
                for (int nt = 0; nt < 8; nt++) {
                    const int n = wn * 64 + nt * 8 + r;
                    uint32_t bh[2];
                    const char* p = sBh + n * ROWB + kb;
                    bh[0] = *(const uint32_t*)(p);
                    bh[1] = *(const uint32_t*)(p + 16);
#pragma unroll
                    for (int mt = 0; mt < 2; mt++) {
                        MMA_F16(acc[mt][nt], ah[mt], bh);
                        if (NT == 3) MMA_F16(acc[mt][nt], al[mt], bh);
                    }
                    if (NT == 3) {
                        uint32_t bl[2];
                        const char* q = sBl + n * ROWB + kb;
                        bl[0] = *(const uint32_t*)(q);
                        bl[1] = *(const uint32_t*)(q + 16);
#pragma unroll
                        for (int mt = 0; mt < 2; mt++)
                            MMA_F16(acc[mt][nt], ah[mt], bl);
                    }
                }
            }

            if (c + 2 < nch) {
                __syncthreads();
                load_stage<NT>(pAh, pAl, pBh, pBl, (c + 2) * KC, ldAB,
                               smem + (c & 1) * STG, tid);
            }
        }

        // epilogue
        if (OUT == 0) {
            float* Cw = C + (size_t)bz * sC
                          + (size_t)(m0 + wm * 32) * ldC + n0 + wn * 64;
#pragma unroll
            for (int mt = 0; mt < 2; mt++)
#pragma unroll
                for (int nt = 0; nt < 8; nt++) {
                    float* p0 = Cw + (size_t)(mt * 16 + r) * ldC + nt * 8 + cq;
                    float* p1 = p0 + 8 * (size_t)ldC;
                    *(float2*)p0 = make_float2(acc[mt][nt][0] * oscale, acc[mt][nt][1] * oscale);
                    *(float2*)p1 = make_float2(acc[mt][nt][2] * oscale, acc[mt][nt][3] * oscale);
                }
        } else if (OUT == 3) {
            // transposed per 4096-row batch: VT[b][n][m']; tiles never straddle batch
            const int gm0 = m0 + wm * 32;
            const int b = gm0 >> 12;
            __half* D = Chi + (size_t)b * AA * SS;
#pragma unroll
            for (int mt = 0; mt < 2; mt++)
#pragma unroll
                for (int nt = 0; nt < 8; nt++) {
                    const int col = n0 + wn * 64 + nt * 8 + cq;
                    const int ms0 = (gm0 + mt * 16 + r) & 4095;
                    const int ms1 = ms0 + 8;
                    D[(size_t)col * SS + ms0]       = __float2half_rn(acc[mt][nt][0] * oscale);
                    D[(size_t)(col + 1) * SS + ms0] = __float2half_rn(acc[mt][nt][1] * oscale);
                    D[(size_t)col * SS + ms1]       = __float2half_rn(acc[mt][nt][2] * oscale);
                    D[(size_t)(col + 1) * SS + ms1] = __float2half_rn(acc[mt][nt][3] * oscale);
                }
        } else {
            const size_t off = (size_t)bz * sC
                             + (size_t)(m0 + wm * 32) * ldC + n0 + wn * 64;
            __half* Hw = Chi + off;
            __half* Lw = (OUT == 1) ? Clo + off : nullptr;
#pragma unroll
            for (int mt = 0; mt < 2; mt++)
#pragma unroll
                for (int nt = 0; nt < 8; nt++) {
                    const size_t o0 = (size_t)(mt * 16 + r) * ldC + nt * 8 + cq;
                    const size_t o1 = o0 + 8 * (size_t)ldC;
                    float x0 = acc[mt][nt][0] * oscale, x1 = acc[mt][nt][1] * oscale;
                    float x2 = acc[mt][nt][2] * oscale, x3 = acc[mt][nt][3] * oscale;
                    __half h0 = __float2half_rn(x0), h1 = __float2half_rn(x1);
                    __half h2 = __float2half_rn(x2), h3 = __float2half_rn(x3);
                    *(__half2*)(Hw + o0) = __halves2half2(h0, h1);
                    *(__half2*)(Hw + o1) = __halves2half2(h2, h3);
                    if (OUT == 1) {
                        __half l0 = __float2half_rn(x0 - __half2float(h0));
                        __half l1 = __float2half_rn(x1 - __half2float(h1));
                        __half l2 = __float2half_rn(x2 - __half2float(h2));
                        __half l3 = __float2half_rn(x3 - __half2float(h3));
                        *(__half2*)(Lw + o0) = __halves2half2(l0, l1);
                        *(__half2*)(Lw + o1) = __halves2half2(l2, l3);
                    }
                }
        }

        __syncthreads();   // smem safe to reuse for next tile
    }
}

// ---------------------------------------------------------------------------
// fp32 -> scaled fp16 hi/lo split (elementwise)
// ---------------------------------------------------------------------------
__global__ __launch_bounds__(256)
void split_plain(const float* __restrict__ in, __half* __restrict__ hi,
                 __half* __restrict__ lo, size_t n, float scale)
{
    size_t i = ((size_t)blockIdx.x * 256 + threadIdx.x) * 4;
    if (i >= n) return;
    float4 x = *(const float4*)(in + i);
    x.x *= scale; x.y *= scale; x.z *= scale; x.w *= scale;
    __half h0 = __float2half_rn(x.x), h1 = __float2half_rn(x.y);
    __half h2 = __float2half_rn(x.z), h3 = __float2half_rn(x.w);
    __half l0 = __float2half_rn(x.x - __half2float(h0));
    __half l1 = __float2half_rn(x.y - __half2float(h1));
    __half l2 = __float2half_rn(x.z - __half2float(h2));
    __half l3 = __float2half_rn(x.w - __half2float(h3));
    *(__half2*)(hi + i)     = __halves2half2(h0, h1);
    *(__half2*)(hi + i + 2) = __halves2half2(h2, h3);
    *(__half2*)(lo + i)     = __halves2half2(l0, l1);
    *(__half2*)(lo + i + 2) = __halves2half2(l2, l3);
}

// Wt split-K reduce: sum 4 partials, scale, split to fp16 hi/lo
__global__ __launch_bounds__(256)
void wt_reduce(const float* __restrict__ part, __half* __restrict__ hi,
               __half* __restrict__ lo, size_t n, float scale)
{
    size_t i = ((size_t)blockIdx.x * 256 + threadIdx.x) * 4;
    if (i >= n) return;
    float4 a = *(const float4*)(part + i);
    float4 b = *(const float4*)(part + n + i);
    float4 c = *(const float4*)(part + 2 * n + i);
    float4 d = *(const float4*)(part + 3 * n + i);
    float x0 = (a.x + b.x + c.x + d.x) * scale;
    float x1 = (a.y + b.y + c.y + d.y) * scale;
    float x2 = (a.z + b.z + c.z + d.z) * scale;
    float x3 = (a.w + b.w + c.w + d.w) * scale;
    __half h0 = __float2half_rn(x0), h1 = __float2half_rn(x1);
    __half h2 = __float2half_rn(x2), h3 = __float2half_rn(x3);
    *(__half2*)(hi + i)     = __halves2half2(h0, h1);
    *(__half2*)(hi + i + 2) = __halves2half2(h2, h3);
    __half l0 = __float2half_rn(x0 - __half2float(h0));
    __half l1 = __float2half_rn(x1 - __half2float(h1));
    __half l2 = __float2half_rn(x2 - __half2float(h2));
    __half l3 = __float2half_rn(x3 - __half2float(h3));
    *(__half2*)(lo + i)     = __halves2half2(l0, l1);
    *(__half2*)(lo + i + 2) = __halves2half2(l2, l3);
}

// fp32 [R,C] -> transposed, scaled fp16 hi only [C,R]
__global__ __launch_bounds__(256)
void transpose_hi16(const float* __restrict__ in, __half* __restrict__ hiT,
                    int R, int C, float scale)
{
    __shared__ float t[32][33];
    const int r0 = blockIdx.y * 32, c0 = blockIdx.x * 32;
    const int tx = threadIdx.x & 31, ty = threadIdx.x >> 5;
#pragma unroll
    for (int i = ty; i < 32; i += 8)
        t[i][tx] = in[(size_t)(r0 + i) * C + c0 + tx];
    __syncthreads();
#pragma unroll
    for (int i = ty; i < 32; i += 8)
        hiT[(size_t)(c0 + i) * R + r0 + tx] = __float2half_rn(t[tx][i] * scale);
}

// ---------------------------------------------------------------------------
// Row softmax (4096 cols), warp-shuffle reductions, write fp16 (hi only)
// ---------------------------------------------------------------------------
__global__ __launch_bounds__(256)
void softmax_f16(const float* __restrict__ S, __half* __restrict__ Ph)
{
    const size_t row = blockIdx.x;
    const float* p = S + row * (size_t)SS;
    const int tid = threadIdx.x;
    const int lane = tid & 31, warp = tid >> 5;
    __shared__ float wred[8];

    float4 v[4];
    float m = -INFINITY;
#pragma unroll
    for (int i = 0; i < 4; i++) {
        v[i] = ((const float4*)p)[tid + i * 256];
        m = fmaxf(m, fmaxf(fmaxf(v[i].x, v[i].y), fmaxf(v[i].z, v[i].w)));
    }
#pragma unroll
    for (int o = 16; o > 0; o >>= 1)
        m = fmaxf(m, __shfl_xor_sync(0xffffffffu, m, o));
    if (lane == 0) wred[warp] = m;
    __syncthreads();
    {
        float t = wred[lane & 7];
#pragma unroll
        for (int o = 4; o > 0; o >>= 1)
            t = fmaxf(t, __shfl_xor_sync(0xffffffffu, t, o, 8));
        m = t;
    }

    float sum = 0.0f;
#pragma unroll
    for (int i = 0; i < 4; i++) {
        v[i].x = __expf(v[i].x - m);
        v[i].y = __expf(v[i].y - m);
        v[i].z = __expf(v[i].z - m);
        v[i].w = __expf(v[i].w - m);
        sum += v[i].x + v[i].y + v[i].z + v[i].w;
    }
#pragma unroll
    for (int o = 16; o > 0; o >>= 1)
        sum += __shfl_xor_sync(0xffffffffu, sum, o);
    __syncthreads();
    if (lane == 0) wred[warp] = sum;
    __syncthreads();
    {
        float t = wred[lane & 7];
#pragma unroll
        for (int o = 4; o > 0; o >>= 1)
            t += __shfl_xor_sync(0xffffffffu, t, o, 8);
        sum = t;
    }
    const float inv = 1.0f / sum;

#pragma unroll
    for (int i = 0; i < 4; i++) {
        size_t o = row * (size_t)SS + (size_t)(tid + i * 256) * 4;
        *(__half2*)(Ph + o)     = __halves2half2(__float2half_rn(v[i].x * inv),
                                                 __float2half_rn(v[i].y * inv));
        *(__half2*)(Ph + o + 2) = __halves2half2(__float2half_rn(v[i].z * inv),
                                                 __float2half_rn(v[i].w * inv));
    }
}

// ---------------------------------------------------------------------------
// kernel_launch — graph-capturable pipeline
//   S = X (Wq Wk^T) X^T  via  Wt = Wk Wq^T (split-K),  Y = X Wt,  S = Y X^T
//   All GEMMs persistent (grid-stride tiles, 2 CTAs/SM) to kill wave quant.
// ---------------------------------------------------------------------------
extern "C" void kernel_launch(void* const* d_in, const int* in_sizes, int n_in,
                              void* d_out, int out_size)
{
    const float* X  = (const float*)d_in[0];
    const float* Wq = (const float*)d_in[1];
    const float* Wk = (const float*)d_in[2];
    const float* Wv = (const float*)d_in[3];
    float* out = (float*)d_out;

    float *Sc, *WtP;
    __half *Xhi, *Xlo, *Wq16h, *Wq16l, *Wk16h, *Wk16l, *WvTh;
    __half *Wth, *Wtl, *Yhi, *Ylo, *Vthi, *Phi;
    cudaGetSymbolAddress((void**)&Sc, g_S);
    cudaGetSymbolAddress((void**)&WtP, g_Wt_part);
    cudaGetSymbolAddress((void**)&Xhi, g_Xhi);
    cudaGetSymbolAddress((void**)&Xlo, g_Xlo);
    cudaGetSymbolAddress((void**)&Wq16h, g_Wq16h);
    cudaGetSymbolAddress((void**)&Wq16l, g_Wq16l);
    cudaGetSymbolAddress((void**)&Wk16h, g_Wk16h);
    cudaGetSymbolAddress((void**)&Wk16l, g_Wk16l);
    cudaGetSymbolAddress((void**)&WvTh, g_WvTh);
    cudaGetSymbolAddress((void**)&Wth, g_Wth);
    cudaGetSymbolAddress((void**)&Wtl, g_Wtl);
    cudaGetSymbolAddress((void**)&Yhi, g_Yhi);
    cudaGetSymbolAddress((void**)&Ylo, g_Ylo);
    cudaGetSymbolAddress((void**)&Vthi, g_Vthi);
    cudaGetSymbolAddress((void**)&Phi, g_Phi);

    int nsm = 148;
    {
        int dev = 0;
        cudaGetDevice(&dev);
        cudaDeviceGetAttribute(&nsm, cudaDevAttrMultiProcessorCount, dev);
    }
    const int NBLK = 2 * nsm;

    const int SMEM_NT3 = 2 * 4 * TILE_T;   // 81920
    const int SMEM_NT1 = 2 * 2 * TILE_T;   // 40960
    cudaFuncSetAttribute(gemm_mma<3,0>, cudaFuncAttributeMaxDynamicSharedMemorySize, SMEM_NT3);
    cudaFuncSetAttribute(gemm_mma<3,1>, cudaFuncAttributeMaxDynamicSharedMemorySize, SMEM_NT3);
    cudaFuncSetAttribute(gemm_mma<1,0>, cudaFuncAttributeMaxDynamicSharedMemorySize, SMEM_NT1);
    cudaFuncSetAttribute(gemm_mma<1,3>, cudaFuncAttributeMaxDynamicSharedMemorySize, SMEM_NT1);

    const float INV16 = 1.0f / 16.0f;

    // 1) splits: X (unscaled), Wq/Wk (x16, no transpose), Wv^T hi (x16)
    split_plain<<<(MTOT * (size_t)DD) / 1024, 256>>>(X, Xhi, Xlo, (size_t)MTOT * DD, 1.0f);
    split_plain<<<((size_t)DD * AA) / 1024, 256>>>(Wq, Wq16h, Wq16l, (size_t)DD * AA, 16.0f);
    split_plain<<<((size_t)DD * AA) / 1024, 256>>>(Wk, Wk16h, Wk16l, (size_t)DD * AA, 16.0f);
    {
        dim3 g(AA / 32, DD / 32, 1);
        transpose_hi16<<<g, 256>>>(Wv, WvTh, DD, AA, 16.0f);
    }

    // 2) Wt = Wk Wq^T (3-term, split-K over 4 slices) -> partials -> reduce
    {
        int gx = DD / 128, gy = DD / 128, gz = 4;
        int nb = gx * gy * gz; if (nb > NBLK) nb = NBLK;
        gemm_mma<3,0><<<nb, 256, SMEM_NT3>>>(Wk16h, Wk16l, Wq16h, Wq16l,
                                             WtP, nullptr, nullptr,
                                             AA / 4, AA, DD,
                                             AA / 4, AA / 4, (long long)DD * DD, 1.0f,
                                             gx, gy, gz);
        wt_reduce<<<((size_t)DD * DD) / 1024, 256>>>(WtP, Wth, Wtl,
                                                     (size_t)DD * DD, INV16);
    }

    // 3) V projection (1-term), epilogue writes V^T per batch directly
    {
        int gx = AA / 128, gy = MTOT / 128, gz = 1;
        int nb = gx * gy; if (nb > NBLK) nb = NBLK;
        gemm_mma<1,3><<<nb, 256, SMEM_NT1>>>(Xhi, nullptr, WvTh, nullptr,
                                             nullptr, Vthi, nullptr,
                                             DD, DD, 0, 0, 0, 0, INV16,
                                             gx, gy, gz);
    }

    // 4) Y = X @ Wt (3-term): raw 16*Y; store Y hi/lo
    {
        int gx = DD / 128, gy = MTOT / 128, gz = 1;
        int nb = gx * gy; if (nb > NBLK) nb = NBLK;
        gemm_mma<3,1><<<nb, 256, SMEM_NT3>>>(Xhi, Xlo, Wth, Wtl,
                                             nullptr, Yhi, Ylo,
                                             DD, DD, DD, 0, 0, 0, INV16,
                                             gx, gy, gz);
    }

    // 5) scores (3-term): S = Y @ X^T per batch
    {
        int gx = SS / 128, gy = SS / 128, gz = BB;
        int nb = gx * gy * gz; if (nb > NBLK) nb = NBLK;
        gemm_mma<3,0><<<nb, 256, SMEM_NT3>>>(Yhi, Ylo, Xhi, Xlo, Sc, nullptr, nullptr,
                                             DD, DD, SS,
                                             (long long)SS * DD, (long long)SS * DD,
                                             (long long)SS * SS, 1.0f,
                                             gx, gy, gz);
    }

    // 6) softmax -> fp16 P (hi only)
    softmax_f16<<<BB * SS, 256>>>(Sc, Phi);

    // 7) output (1-term): O = P @ V per batch
    {
        int gx = AA / 128, gy = SS / 128, gz = BB;
        int nb = gx * gy * gz; if (nb > NBLK) nb = NBLK;
        gemm_mma<1,0><<<nb, 256, SMEM_NT1>>>(Phi, nullptr, Vthi, nullptr,
                                             out, nullptr, nullptr,
                                             SS, SS, AA,
                                             (long long)SS * SS, (long long)AA * SS,
                                             (long long)SS * AA, 1.0f,
                                             gx, gy, gz);
    }
}

// round 15
// speedup vs baseline: 1.0698x; 1.0698x over previous
#include <cuda_runtime.h>
#include <cuda_fp16.h>
#include <cstdint>
#include <math.h>

// Problem dims (fixed)
#define BB 4
#define SS 4096
#define DD 1024
#define AA 1024
#define MTOT (BB*SS)   // 16384

// ---------------------------------------------------------------------------
// Device scratch
// ---------------------------------------------------------------------------
__device__ float g_S [(size_t)BB * SS * SS];              // 256 MB scores
__device__ float g_Wt_part[4 * (size_t)DD * DD];          // 16 MB split-K partials
__device__ __half g_Xhi[(size_t)MTOT * DD];
__device__ __half g_Xlo[(size_t)MTOT * DD];
__device__ __half g_Wqk16h[2 * (size_t)DD * AA];          // 16*{Wq,Wk} hi (row-major)
__device__ __half g_Wqk16l[2 * (size_t)DD * AA];          // 16*{Wq,Wk} lo
__device__ __half g_WvTh[(size_t)AA * DD];                // (16*Wv)^T hi [A,D]
__device__ __half g_Wth[(size_t)DD * DD];                 // 16*W~ hi/lo
__device__ __half g_Wtl[(size_t)DD * DD];
__device__ __half g_Yhi[(size_t)MTOT * DD];               // Y = X*W~ split
__device__ __half g_Ylo[(size_t)MTOT * DD];
__device__ __half g_Vthi[(size_t)BB * AA * SS];           // V^T per batch [A,S]
__device__ __half g_Phi[(size_t)BB * SS * SS];            // 128 MB

// ---------------------------------------------------------------------------
// Helpers
// ---------------------------------------------------------------------------
__device__ __forceinline__ uint32_t smem_u32(const void* p) {
    uint32_t a;
    asm("{ .reg .u64 t; cvta.to.shared.u64 t, %1; cvt.u32.u64 %0, t; }" : "=r"(a) : "l"(p));
    return a;
}

#define CP_ASYNC16(saddr, gaddr) \
    asm volatile("cp.async.cg.shared.global [%0], [%1], 16;" :: "r"(saddr), "l"(gaddr))
#define CP_COMMIT()  asm volatile("cp.async.commit_group;" ::: "memory")
#define CP_WAIT1()   asm volatile("cp.async.wait_group 1;" ::: "memory")
#define CP_WAIT0()   asm volatile("cp.async.wait_group 0;" ::: "memory")

#define MMA_F16(c, a, b) \
    asm volatile("mma.sync.aligned.m16n8k16.row.col.f32.f16.f16.f32 " \
        "{%0,%1,%2,%3}, {%4,%5,%6,%7}, {%8,%9}, {%0,%1,%2,%3};" \
        : "+f"((c)[0]), "+f"((c)[1]), "+f"((c)[2]), "+f"((c)[3]) \
        : "r"((a)[0]), "r"((a)[1]), "r"((a)[2]), "r"((a)[3]), \
          "r"((b)[0]), "r"((b)[1]))

// ---------------------------------------------------------------------------
// HMMA GEMM, fp16 hi/lo split, term count NT (all f32-accumulate):
//   NT=3: AhBh + AlBh + AhBl ; NT=1: AhBh
// OUT: 0 = fp32 C (strided by sC per z); 1 = fp16 hi/lo (Chi,Clo);
//      3 = fp16 hi transposed per 4096-row batch (V^T)
// C[M,N] = A[M,K] * B[N,K]^T. ldAB = row stride of A/B; K = reduction length
// consumed (k-slice via sA/sB offsets). CTA 128x128, KC=32, 2-stage cp.async,
// 2 CTAs/SM, warp tile 32x64.
// ---------------------------------------------------------------------------
#define KC    32
#define ROWB  80                              // 32 fp16 (64B) + 16B pad
#define TILE_T (128 * ROWB)                   // 10240 B

__device__ __forceinline__ void load_tile32(const __half* __restrict__ g,
                                            int ldK, char* sb, int tid)
{
#pragma unroll
    for (int i = 0; i < 2; i++) {
        int ch = tid + i * 256;               // 0..511
        int row = ch >> 2, c = ch & 3;
        CP_ASYNC16(smem_u32(sb + row * ROWB + c * 16),
                   g + (size_t)row * ldK + c * 8);
    }
}

template <int NT>
__device__ __forceinline__ void load_stage(const __half* pAh, const __half* pAl,
                                           const __half* pBh, const __half* pBl,
                                           int k0, int ldAB, char* sp, int tid)
{
    load_tile32(pAh + k0, ldAB, sp, tid);
    if (NT == 3) {
        load_tile32(pAl + k0, ldAB, sp + TILE_T,     tid);
        load_tile32(pBh + k0, ldAB, sp + 2 * TILE_T, tid);
        load_tile32(pBl + k0, ldAB, sp + 3 * TILE_T, tid);
    } else {
        load_tile32(pBh + k0, ldAB, sp + TILE_T, tid);
    }
    CP_COMMIT();
}

template <int NT, int OUT>
__global__ __launch_bounds__(256, 2)
void gemm_mma(const __half* __restrict__ Ahi, const __half* __restrict__ Alo,
              const __half* __restrict__ Bhi, const __half* __restrict__ Blo,
              float* __restrict__ C,
              __half* __restrict__ Chi, __half* __restrict__ Clo,
              int K, int ldAB, int ldC,
              long long sA, long long sB, long long sC, float oscale)
{
    constexpr int STG = (NT == 3 ? 4 : 2) * TILE_T;
    extern __shared__ __align__(128) char smem[];
    const int tid = threadIdx.x;
    const int wid = tid >> 5, lane = tid & 31;
    const int wm = wid & 3, wn = wid >> 2;    // 4(m) x 2(n)
    const int m0 = blockIdx.y * 128;
    const int n0 = blockIdx.x * 128;

    const __half* pAh = Ahi + (size_t)blockIdx.z * sA + (size_t)m0 * ldAB;
    const __half* pAl = (NT == 3) ? Alo + (size_t)blockIdx.z * sA + (size_t)m0 * ldAB : nullptr;
    const __half* pBh = Bhi + (size_t)blockIdx.z * sB + (size_t)n0 * ldAB;
    const __half* pBl = (NT == 3) ? Blo + (size_t)blockIdx.z * sB + (size_t)n0 * ldAB : nullptr;

    float acc[2][8][4];
#pragma unroll
    for (int mt = 0; mt < 2; mt++)
#pragma unroll
        for (int nt = 0; nt < 8; nt++)
#pragma unroll
            for (int j = 0; j < 4; j++) acc[mt][nt][j] = 0.0f;

    const int nch = K >> 5;

    load_stage<NT>(pAh, pAl, pBh, pBl, 0,  ldAB, smem,       tid);
    load_stage<NT>(pAh, pAl, pBh, pBl, KC, ldAB, smem + STG, tid);

    const int r  = lane >> 2;        // 0..7
    const int kq = lane & 3;         // 0..3

    for (int c = 0; c < nch; ++c) {
        if (c + 1 < nch) CP_WAIT1(); else CP_WAIT0();
        __syncthreads();

        const char* sp  = smem + (c & 1) * STG;
        const char* sAh = sp;
        const char* sAl = sp + TILE_T;                       // NT==3
        const char* sBh = sp + (NT == 3 ? 2 : 1) * TILE_T;
        const char* sBl = sp + 3 * TILE_T;                   // NT==3

#pragma unroll
        for (int ks = 0; ks < 2; ++ks) {
            const int kb = ks * 32 + kq * 4;

            uint32_t ah[2][4], al[2][4];
#pragma unroll
            for (int mt = 0; mt < 2; mt++) {
                const int row = wm * 32 + mt * 16 + r;
                const char* a0 = sAh + row * ROWB + kb;
                const char* a1 = sAh + (row + 8) * ROWB + kb;
                ah[mt][0] = *(const uint32_t*)(a0);
                ah[mt][1] = *(const uint32_t*)(a1);
                ah[mt][2] = *(const uint32_t*)(a0 + 16);
                ah[mt][3] = *(const uint32_t*)(a1 + 16);
                if (NT == 3) {
                    const char* b0 = sAl + row * ROWB + kb;
                    const char* b1 = sAl + (row + 8) * ROWB + kb;
                    al[mt][0] = *(const uint32_t*)(b0);
                    al[mt][1] = *(const uint32_t*)(b1);
                    al[mt][2] = *(const uint32_t*)(b0 + 16);
                    al[mt][3] = *(const uint32_t*)(b1 + 16);
                }
            }
#pragma unroll
            for (int nt = 0; nt < 8; nt++) {
                const int n = wn * 64 + nt * 8 + r;
                uint32_t bh[2];
                const char* p = sBh + n * ROWB + kb;
                bh[0] = *(const uint32_t*)(p);
                bh[1] = *(const uint32_t*)(p + 16);
#pragma unroll
                for (int mt = 0; mt < 2; mt++) {
                    MMA_F16(acc[mt][nt], ah[mt], bh);
                    if (NT == 3) MMA_F16(acc[mt][nt], al[mt], bh);
                }
                if (NT == 3) {
                    uint32_t bl[2];
                    const char* q = sBl + n * ROWB + kb;
                    bl[0] = *(const uint32_t*)(q);
                    bl[1] = *(const uint32_t*)(q + 16);
#pragma unroll
                    for (int mt = 0; mt < 2; mt++)
                        MMA_F16(acc[mt][nt], ah[mt], bl);
                }
            }
        }

        if (c + 2 < nch) {
            __syncthreads();
            load_stage<NT>(pAh, pAl, pBh, pBl, (c + 2) * KC, ldAB,
                           smem + (c & 1) * STG, tid);
        }
    }

    // epilogue
    const int cq = (lane & 3) * 2;
    if (OUT == 0) {
        float* Cw = C + (size_t)blockIdx.z * sC
                      + (size_t)(m0 + wm * 32) * ldC + n0 + wn * 64;
#pragma unroll
        for (int mt = 0; mt < 2; mt++)
#pragma unroll
            for (int nt = 0; nt < 8; nt++) {
                float* p0 = Cw + (size_t)(mt * 16 + r) * ldC + nt * 8 + cq;
                float* p1 = p0 + 8 * (size_t)ldC;
                *(float2*)p0 = make_float2(acc[mt][nt][0] * oscale, acc[mt][nt][1] * oscale);
                *(float2*)p1 = make_float2(acc[mt][nt][2] * oscale, acc[mt][nt][3] * oscale);
            }
    } else if (OUT == 3) {
        // transposed per 4096-row batch: VT[b][n][m']; tiles never straddle batch
        const int gm0 = m0 + wm * 32;
        const int b = gm0 >> 12;
        __half* D = Chi + (size_t)b * AA * SS;
#pragma unroll
        for (int mt = 0; mt < 2; mt++)
#pragma unroll
            for (int nt = 0; nt < 8; nt++) {
                const int col = n0 + wn * 64 + nt * 8 + cq;
                const int ms0 = (gm0 + mt * 16 + r) & 4095;
                const int ms1 = ms0 + 8;
                D[(size_t)col * SS + ms0]       = __float2half_rn(acc[mt][nt][0] * oscale);
                D[(size_t)(col + 1) * SS + ms0] = __float2half_rn(acc[mt][nt][1] * oscale);
                D[(size_t)col * SS + ms1]       = __float2half_rn(acc[mt][nt][2] * oscale);
                D[(size_t)(col + 1) * SS + ms1] = __float2half_rn(acc[mt][nt][3] * oscale);
            }
    } else {
        const size_t off = (size_t)blockIdx.z * sC
                         + (size_t)(m0 + wm * 32) * ldC + n0 + wn * 64;
        __half* Hw = Chi + off;
        __half* Lw = Clo + off;
#pragma unroll
        for (int mt = 0; mt < 2; mt++)
#pragma unroll
            for (int nt = 0; nt < 8; nt++) {
                const size_t o0 = (size_t)(mt * 16 + r) * ldC + nt * 8 + cq;
                const size_t o1 = o0 + 8 * (size_t)ldC;
                float x0 = acc[mt][nt][0] * oscale, x1 = acc[mt][nt][1] * oscale;
                float x2 = acc[mt][nt][2] * oscale, x3 = acc[mt][nt][3] * oscale;
                __half h0 = __float2half_rn(x0), h1 = __float2half_rn(x1);
                __half h2 = __float2half_rn(x2), h3 = __float2half_rn(x3);
                *(__half2*)(Hw + o0) = __halves2half2(h0, h1);
                *(__half2*)(Hw + o1) = __halves2half2(h2, h3);
                __half l0 = __float2half_rn(x0 - __half2float(h0));
                __half l1 = __float2half_rn(x1 - __half2float(h1));
                __half l2 = __float2half_rn(x2 - __half2float(h2));
                __half l3 = __float2half_rn(x3 - __half2float(h3));
                *(__half2*)(Lw + o0) = __halves2half2(l0, l1);
                *(__half2*)(Lw + o1) = __halves2half2(l2, l3);
            }
    }
}

// ---------------------------------------------------------------------------
// fp32 -> scaled fp16 hi/lo split (elementwise)
// ---------------------------------------------------------------------------
__global__ __launch_bounds__(256)
void split_plain(const float* __restrict__ in, __half* __restrict__ hi,
                 __half* __restrict__ lo, size_t n, float scale)
{
    size_t i = ((size_t)blockIdx.x * 256 + threadIdx.x) * 4;
    if (i >= n) return;
    float4 x = *(const float4*)(in + i);
    x.x *= scale; x.y *= scale; x.z *= scale; x.w *= scale;
    __half h0 = __float2half_rn(x.x), h1 = __float2half_rn(x.y);
    __half h2 = __float2half_rn(x.z), h3 = __float2half_rn(x.w);
    __half l0 = __float2half_rn(x.x - __half2float(h0));
    __half l1 = __float2half_rn(x.y - __half2float(h1));
    __half l2 = __float2half_rn(x.z - __half2float(h2));
    __half l3 = __float2half_rn(x.w - __half2float(h3));
    *(__half2*)(hi + i)     = __halves2half2(h0, h1);
    *(__half2*)(hi + i + 2) = __halves2half2(h2, h3);
    *(__half2*)(lo + i)     = __halves2half2(l0, l1);
    *(__half2*)(lo + i + 2) = __halves2half2(l2, l3);
}

// Two-source variant: z selects {Wq, Wk}; writes into stacked dst at z*n
__global__ __launch_bounds__(256)
void split_plain2(const float* __restrict__ inA, const float* __restrict__ inB,
                  __half* __restrict__ hi, __half* __restrict__ lo,
                  size_t n, float scale)
{
    const float* in = blockIdx.y ? inB : inA;
    size_t base = (size_t)blockIdx.y * n;
    size_t i = ((size_t)blockIdx.x * 256 + threadIdx.x) * 4;
    if (i >= n) return;
    float4 x = *(const float4*)(in + i);
    x.x *= scale; x.y *= scale; x.z *= scale; x.w *= scale;
    __half h0 = __float2half_rn(x.x), h1 = __float2half_rn(x.y);
    __half h2 = __float2half_rn(x.z), h3 = __float2half_rn(x.w);
    __half l0 = __float2half_rn(x.x - __half2float(h0));
    __half l1 = __float2half_rn(x.y - __half2float(h1));
    __half l2 = __float2half_rn(x.z - __half2float(h2));
    __half l3 = __float2half_rn(x.w - __half2float(h3));
    *(__half2*)(hi + base + i)     = __halves2half2(h0, h1);
    *(__half2*)(hi + base + i + 2) = __halves2half2(h2, h3);
    *(__half2*)(lo + base + i)     = __halves2half2(l0, l1);
    *(__half2*)(lo + base + i + 2) = __halves2half2(l2, l3);
}

// Wt split-K reduce: sum 4 partials, scale, split to fp16 hi/lo
__global__ __launch_bounds__(256)
void wt_reduce(const float* __restrict__ part, __half* __restrict__ hi,
               __half* __restrict__ lo, size_t n, float scale)
{
    size_t i = ((size_t)blockIdx.x * 256 + threadIdx.x) * 4;
    if (i >= n) return;
    float4 a = *(const float4*)(part + i);
    float4 b = *(const float4*)(part + n + i);
    float4 c = *(const float4*)(part + 2 * n + i);
    float4 d = *(const float4*)(part + 3 * n + i);
    float x0 = (a.x + b.x + c.x + d.x) * scale;
    float x1 = (a.y + b.y + c.y + d.y) * scale;
    float x2 = (a.z + b.z + c.z + d.z) * scale;
    float x3 = (a.w + b.w + c.w + d.w) * scale;
    __half h0 = __float2half_rn(x0), h1 = __float2half_rn(x1);
    __half h2 = __float2half_rn(x2), h3 = __float2half_rn(x3);
    *(__half2*)(hi + i)     = __halves2half2(h0, h1);
    *(__half2*)(hi + i + 2) = __halves2half2(h2, h3);
    __half l0 = __float2half_rn(x0 - __half2float(h0));
    __half l1 = __float2half_rn(x1 - __half2float(h1));
    __half l2 = __float2half_rn(x2 - __half2float(h2));
    __half l3 = __float2half_rn(x3 - __half2float(h3));
    *(__half2*)(lo + i)     = __halves2half2(l0, l1);
    *(__half2*)(lo + i + 2) = __halves2half2(l2, l3);
}

// fp32 [R,C] -> transposed, scaled fp16 hi only [C,R]
__global__ __launch_bounds__(256)
void transpose_hi16(const float* __restrict__ in, __half* __restrict__ hiT,
                    int R, int C, float scale)
{
    __shared__ float t[32][33];
    const int r0 = blockIdx.y * 32, c0 = blockIdx.x * 32;
    const int tx = threadIdx.x & 31, ty = threadIdx.x >> 5;
#pragma unroll
    for (int i = ty; i < 32; i += 8)
        t[i][tx] = in[(size_t)(r0 + i) * C + c0 + tx];
    __syncthreads();
#pragma unroll
    for (int i = ty; i < 32; i += 8)
        hiT[(size_t)(c0 + i) * R + r0 + tx] = __float2half_rn(t[tx][i] * scale);
}

// ---------------------------------------------------------------------------
// Row softmax (4096 cols), warp-shuffle reductions, write fp16 (hi only)
// ---------------------------------------------------------------------------
__global__ __launch_bounds__(256)
void softmax_f16(const float* __restrict__ S, __half* __restrict__ Ph)
{
    const size_t row = blockIdx.x;
    const float* p = S + row * (size_t)SS;
    const int tid = threadIdx.x;
    const int lane = tid & 31, warp = tid >> 5;
    __shared__ float wred[8];

    float4 v[4];
    float m = -INFINITY;
#pragma unroll
    for (int i = 0; i < 4; i++) {
        v[i] = ((const float4*)p)[tid + i * 256];
        m = fmaxf(m, fmaxf(fmaxf(v[i].x, v[i].y), fmaxf(v[i].z, v[i].w)));
    }
#pragma unroll
    for (int o = 16; o > 0; o >>= 1)
        m = fmaxf(m, __shfl_xor_sync(0xffffffffu, m, o));
    if (lane == 0) wred[warp] = m;
    __syncthreads();
    {
        float t = wred[lane & 7];
#pragma unroll
        for (int o = 4; o > 0; o >>= 1)
            t = fmaxf(t, __shfl_xor_sync(0xffffffffu, t, o, 8));
        m = t;
    }

    float sum = 0.0f;
#pragma unroll
    for (int i = 0; i < 4; i++) {
        v[i].x = __expf(v[i].x - m);
        v[i].y = __expf(v[i].y - m);
        v[i].z = __expf(v[i].z - m);
        v[i].w = __expf(v[i].w - m);
        sum += v[i].x + v[i].y + v[i].z + v[i].w;
    }
#pragma unroll
    for (int o = 16; o > 0; o >>= 1)
        sum += __shfl_xor_sync(0xffffffffu, sum, o);
    __syncthreads();
    if (lane == 0) wred[warp] = sum;
    __syncthreads();
    {
        float t = wred[lane & 7];
#pragma unroll
        for (int o = 4; o > 0; o >>= 1)
            t += __shfl_xor_sync(0xffffffffu, t, o, 8);
        sum = t;
    }
    const float inv = 1.0f / sum;

#pragma unroll
    for (int i = 0; i < 4; i++) {
        size_t o = row * (size_t)SS + (size_t)(tid + i * 256) * 4;
        *(__half2*)(Ph + o)     = __halves2half2(__float2half_rn(v[i].x * inv),
                                                 __float2half_rn(v[i].y * inv));
        *(__half2*)(Ph + o + 2) = __halves2half2(__float2half_rn(v[i].z * inv),
                                                 __float2half_rn(v[i].w * inv));
    }
}

// ---------------------------------------------------------------------------
// kernel_launch — graph-capturable pipeline (classic grids — R13 config)
//   S = X (Wq Wk^T) X^T  via  Wt = Wk Wq^T (split-K),  Y = X Wt,  S = Y X^T
// ---------------------------------------------------------------------------
extern "C" void kernel_launch(void* const* d_in, const int* in_sizes, int n_in,
                              void* d_out, int out_size)
{
    const float* X  = (const float*)d_in[0];
    const float* Wq = (const float*)d_in[1];
    const float* Wk = (const float*)d_in[2];
    const float* Wv = (const float*)d_in[3];
    float* out = (float*)d_out;

    float *Sc, *WtP;
    __half *Xhi, *Xlo, *Wqkh, *Wqkl, *WvTh;
    __half *Wth, *Wtl, *Yhi, *Ylo, *Vthi, *Phi;
    cudaGetSymbolAddress((void**)&Sc, g_S);
    cudaGetSymbolAddress((void**)&WtP, g_Wt_part);
    cudaGetSymbolAddress((void**)&Xhi, g_Xhi);
    cudaGetSymbolAddress((void**)&Xlo, g_Xlo);
    cudaGetSymbolAddress((void**)&Wqkh, g_Wqk16h);
    cudaGetSymbolAddress((void**)&Wqkl, g_Wqk16l);
    cudaGetSymbolAddress((void**)&WvTh, g_WvTh);
    cudaGetSymbolAddress((void**)&Wth, g_Wth);
    cudaGetSymbolAddress((void**)&Wtl, g_Wtl);
    cudaGetSymbolAddress((void**)&Yhi, g_Yhi);
    cudaGetSymbolAddress((void**)&Ylo, g_Ylo);
    cudaGetSymbolAddress((void**)&Vthi, g_Vthi);
    cudaGetSymbolAddress((void**)&Phi, g_Phi);

    const size_t WSZ = (size_t)DD * AA;
    __half* Wq16h = Wqkh;            // z=0 slot
    __half* Wq16l = Wqkl;
    __half* Wk16h = Wqkh + WSZ;      // z=1 slot
    __half* Wk16l = Wqkl + WSZ;

    const int SMEM_NT3 = 2 * 4 * TILE_T;   // 81920
    const int SMEM_NT1 = 2 * 2 * TILE_T;   // 40960
    cudaFuncSetAttribute(gemm_mma<3,0>, cudaFuncAttributeMaxDynamicSharedMemorySize, SMEM_NT3);
    cudaFuncSetAttribute(gemm_mma<3,1>, cudaFuncAttributeMaxDynamicSharedMemorySize, SMEM_NT3);
    cudaFuncSetAttribute(gemm_mma<1,0>, cudaFuncAttributeMaxDynamicSharedMemorySize, SMEM_NT1);
    cudaFuncSetAttribute(gemm_mma<1,3>, cudaFuncAttributeMaxDynamicSharedMemorySize, SMEM_NT1);

    const float INV16 = 1.0f / 16.0f;

    // 1) splits: X (unscaled), Wq+Wk (x16, one batched launch), Wv^T hi (x16)
    split_plain<<<(MTOT * (size_t)DD) / 1024, 256>>>(X, Xhi, Xlo, (size_t)MTOT * DD, 1.0f);
    {
        dim3 g((unsigned)(WSZ / 1024), 2, 1);
        split_plain2<<<g, 256>>>(Wq, Wk, Wqkh, Wqkl, WSZ, 16.0f);
    }
    {
        dim3 g(AA / 32, DD / 32, 1);
        transpose_hi16<<<g, 256>>>(Wv, WvTh, DD, AA, 16.0f);
    }

    // 2) Wt = Wk Wq^T (3-term, split-K over 4 slices) -> partials -> reduce
    {
        dim3 g(DD / 128, DD / 128, 4);
        gemm_mma<3,0><<<g, 256, SMEM_NT3>>>(Wk16h, Wk16l, Wq16h, Wq16l,
                                            WtP, nullptr, nullptr,
                                            AA / 4, AA, DD,
                                            AA / 4, AA / 4, (long long)DD * DD, 1.0f);
        wt_reduce<<<((size_t)DD * DD) / 1024, 256>>>(WtP, Wth, Wtl,
                                                     (size_t)DD * DD, INV16);
    }

    // 3) V projection (1-term), epilogue writes V^T per batch directly
    {
        dim3 g(AA / 128, MTOT / 128, 1);
        gemm_mma<1,3><<<g, 256, SMEM_NT1>>>(Xhi, nullptr, WvTh, nullptr,
                                            nullptr, Vthi, nullptr,
                                            DD, DD, 0, 0, 0, 0, INV16);
    }

    // 4) Y = X @ Wt (3-term): raw 16*Y; store Y hi/lo
    {
        dim3 g(DD / 128, MTOT / 128, 1);
        gemm_mma<3,1><<<g, 256, SMEM_NT3>>>(Xhi, Xlo, Wth, Wtl,
                                            nullptr, Yhi, Ylo,
                                            DD, DD, DD, 0, 0, 0, INV16);
    }

    // 5) scores (3-term): S = Y @ X^T per batch
    {
        dim3 g(SS / 128, SS / 128, BB);
        gemm_mma<3,0><<<g, 256, SMEM_NT3>>>(Yhi, Ylo, Xhi, Xlo, Sc, nullptr, nullptr,
                                            DD, DD, SS,
                                            (long long)SS * DD, (long long)SS * DD,
                                            (long long)SS * SS, 1.0f);
    }

    // 6) softmax -> fp16 P (hi only)
    softmax_f16<<<BB * SS, 256>>>(Sc, Phi);

    // 7) output (1-term): O = P @ V per batch
    {
        dim3 g(AA / 128, SS / 128, BB);
        gemm_mma<1,0><<<g, 256, SMEM_NT1>>>(Phi, nullptr, Vthi, nullptr,
                                            out, nullptr, nullptr,
                                            SS, SS, AA,
                                            (long long)SS * SS, (long long)AA * SS,
                                            (long long)SS * AA, 1.0f);
    }
}

// round 16
// speedup vs baseline: 1.0789x; 1.0085x over previous
#include <cuda_runtime.h>
#include <cuda_fp16.h>
#include <cstdint>
#include <math.h>

// Problem dims (fixed)
#define BB 4
#define SS 4096
#define DD 1024
#define AA 1024
#define MTOT (BB*SS)   // 16384

// ---------------------------------------------------------------------------
// Device scratch
// ---------------------------------------------------------------------------
__device__ float g_S [(size_t)BB * SS * SS];              // 256 MB scores
__device__ float g_Wt_part[4 * (size_t)DD * DD];          // 16 MB split-K partials
__device__ __half g_Xhi[(size_t)MTOT * DD];
__device__ __half g_Xlo[(size_t)MTOT * DD];
__device__ __half g_Wqk16h[2 * (size_t)DD * AA];          // 16*{Wq,Wk} hi (row-major)
__device__ __half g_Wqk16l[2 * (size_t)DD * AA];          // 16*{Wq,Wk} lo
__device__ __half g_WvTh[(size_t)AA * DD];                // (16*Wv)^T hi [A,D]
__device__ __half g_Wth[(size_t)DD * DD];                 // 16*W~ hi/lo
__device__ __half g_Wtl[(size_t)DD * DD];
__device__ __half g_Yhi[(size_t)MTOT * DD];               // Y = X*W~ split
__device__ __half g_Ylo[(size_t)MTOT * DD];
__device__ __half g_Vthi[(size_t)BB * AA * SS];           // V^T per batch [A,S]
__device__ __half g_Phi[(size_t)BB * SS * SS];            // 128 MB

// ---------------------------------------------------------------------------
// Helpers
// ---------------------------------------------------------------------------
__device__ __forceinline__ uint32_t smem_u32(const void* p) {
    uint32_t a;
    asm("{ .reg .u64 t; cvta.to.shared.u64 t, %1; cvt.u32.u64 %0, t; }" : "=r"(a) : "l"(p));
    return a;
}

#define CP_ASYNC16(saddr, gaddr) \
    asm volatile("cp.async.cg.shared.global [%0], [%1], 16;" :: "r"(saddr), "l"(gaddr))
#define CP_COMMIT()  asm volatile("cp.async.commit_group;" ::: "memory")
#define CP_WAIT1()   asm volatile("cp.async.wait_group 1;" ::: "memory")
#define CP_WAIT0()   asm volatile("cp.async.wait_group 0;" ::: "memory")

#define MMA_F16(c, a, b) \
    asm volatile("mma.sync.aligned.m16n8k16.row.col.f32.f16.f16.f32 " \
        "{%0,%1,%2,%3}, {%4,%5,%6,%7}, {%8,%9}, {%0,%1,%2,%3};" \
        : "+f"((c)[0]), "+f"((c)[1]), "+f"((c)[2]), "+f"((c)[3]) \
        : "r"((a)[0]), "r"((a)[1]), "r"((a)[2]), "r"((a)[3]), \
          "r"((b)[0]), "r"((b)[1]))

// ---------------------------------------------------------------------------
// HMMA GEMM, fp16 hi/lo split, term count NT (all f32-accumulate):
//   NT=3: AhBh + AlBh + AhBl ; NT=1: AhBh
// OUT: 0 = fp32 C (strided by sC per z); 1 = fp16 hi/lo (Chi,Clo);
//      3 = fp16 hi transposed per 4096-row batch (V^T)
// C[M,N] = A[M,K] * B[N,K]^T. ldAB = row stride of A/B; K = reduction length
// consumed (k-slice via sA/sB offsets). CTA 128x128, KC=32, 2-stage cp.async,
// 2 CTAs/SM, warp tile 32x64.
// ---------------------------------------------------------------------------
#define KC    32
#define ROWB  80                              // 32 fp16 (64B) + 16B pad
#define TILE_T (128 * ROWB)                   // 10240 B

__device__ __forceinline__ void load_tile32(const __half* __restrict__ g,
                                            int ldK, char* sb, int tid)
{
#pragma unroll
    for (int i = 0; i < 2; i++) {
        int ch = tid + i * 256;               // 0..511
        int row = ch >> 2, c = ch & 3;
        CP_ASYNC16(smem_u32(sb + row * ROWB + c * 16),
                   g + (size_t)row * ldK + c * 8);
    }
}

template <int NT>
__device__ __forceinline__ void load_stage(const __half* pAh, const __half* pAl,
                                           const __half* pBh, const __half* pBl,
                                           int k0, int ldAB, char* sp, int tid)
{
    load_tile32(pAh + k0, ldAB, sp, tid);
    if (NT == 3) {
        load_tile32(pAl + k0, ldAB, sp + TILE_T,     tid);
        load_tile32(pBh + k0, ldAB, sp + 2 * TILE_T, tid);
        load_tile32(pBl + k0, ldAB, sp + 3 * TILE_T, tid);
    } else {
        load_tile32(pBh + k0, ldAB, sp + TILE_T, tid);
    }
    CP_COMMIT();
}

template <int NT, int OUT>
__global__ __launch_bounds__(256, 2)
void gemm_mma(const __half* __restrict__ Ahi, const __half* __restrict__ Alo,
              const __half* __restrict__ Bhi, const __half* __restrict__ Blo,
              float* __restrict__ C,
              __half* __restrict__ Chi, __half* __restrict__ Clo,
              int K, int ldAB, int ldC,
              long long sA, long long sB, long long sC, float oscale)
{
    constexpr int STG = (NT == 3 ? 4 : 2) * TILE_T;
    extern __shared__ __align__(128) char smem[];
    const int tid = threadIdx.x;
    const int wid = tid >> 5, lane = tid & 31;
    const int wm = wid & 3, wn = wid >> 2;    // 4(m) x 2(n)
    const int m0 = blockIdx.y * 128;
    const int n0 = blockIdx.x * 128;

    const __half* pAh = Ahi + (size_t)blockIdx.z * sA + (size_t)m0 * ldAB;
    const __half* pAl = (NT == 3) ? Alo + (size_t)blockIdx.z * sA + (size_t)m0 * ldAB : nullptr;
    const __half* pBh = Bhi + (size_t)blockIdx.z * sB + (size_t)n0 * ldAB;
    const __half* pBl = (NT == 3) ? Blo + (size_t)blockIdx.z * sB + (size_t)n0 * ldAB : nullptr;

    float acc[2][8][4];
#pragma unroll
    for (int mt = 0; mt < 2; mt++)
#pragma unroll
        for (int nt = 0; nt < 8; nt++)
#pragma unroll
            for (int j = 0; j < 4; j++) acc[mt][nt][j] = 0.0f;

    const int nch = K >> 5;

    load_stage<NT>(pAh, pAl, pBh, pBl, 0,  ldAB, smem,       tid);
    load_stage<NT>(pAh, pAl, pBh, pBl, KC, ldAB, smem + STG, tid);

    const int r  = lane >> 2;        // 0..7
    const int kq = lane & 3;         // 0..3

    for (int c = 0; c < nch; ++c) {
        if (c + 1 < nch) CP_WAIT1(); else CP_WAIT0();
        __syncthreads();

        const char* sp  = smem + (c & 1) * STG;
        const char* sAh = sp;
        const char* sAl = sp + TILE_T;                       // NT==3
        const char* sBh = sp + (NT == 3 ? 2 : 1) * TILE_T;
        const char* sBl = sp + 3 * TILE_T;                   // NT==3

#pragma unroll
        for (int ks = 0; ks < 2; ++ks) {
            const int kb = ks * 32 + kq * 4;

            uint32_t ah[2][4], al[2][4];
#pragma unroll
            for (int mt = 0; mt < 2; mt++) {
                const int row = wm * 32 + mt * 16 + r;
                const char* a0 = sAh + row * ROWB + kb;
                const char* a1 = sAh + (row + 8) * ROWB + kb;
                ah[mt][0] = *(const uint32_t*)(a0);
                ah[mt][1] = *(const uint32_t*)(a1);
                ah[mt][2] = *(const uint32_t*)(a0 + 16);
                ah[mt][3] = *(const uint32_t*)(a1 + 16);
                if (NT == 3) {
                    const char* b0 = sAl + row * ROWB + kb;
                    const char* b1 = sAl + (row + 8) * ROWB + kb;
                    al[mt][0] = *(const uint32_t*)(b0);
                    al[mt][1] = *(const uint32_t*)(b1);
                    al[mt][2] = *(const uint32_t*)(b0 + 16);
                    al[mt][3] = *(const uint32_t*)(b1 + 16);
                }
            }
#pragma unroll
            for (int nt = 0; nt < 8; nt++) {
                const int n = wn * 64 + nt * 8 + r;
                uint32_t bh[2];
                const char* p = sBh + n * ROWB + kb;
                bh[0] = *(const uint32_t*)(p);
                bh[1] = *(const uint32_t*)(p + 16);
#pragma unroll
                for (int mt = 0; mt < 2; mt++) {
                    MMA_F16(acc[mt][nt], ah[mt], bh);
                    if (NT == 3) MMA_F16(acc[mt][nt], al[mt], bh);
                }
                if (NT == 3) {
                    uint32_t bl[2];
                    const char* q = sBl + n * ROWB + kb;
                    bl[0] = *(const uint32_t*)(q);
                    bl[1] = *(const uint32_t*)(q + 16);
#pragma unroll
                    for (int mt = 0; mt < 2; mt++)
                        MMA_F16(acc[mt][nt], ah[mt], bl);
                }
            }
        }

        if (c + 2 < nch) {
            __syncthreads();
            load_stage<NT>(pAh, pAl, pBh, pBl, (c + 2) * KC, ldAB,
                           smem + (c & 1) * STG, tid);
        }
    }

    // epilogue
    const int cq = (lane & 3) * 2;
    if (OUT == 0) {
        float* Cw = C + (size_t)blockIdx.z * sC
                      + (size_t)(m0 + wm * 32) * ldC + n0 + wn * 64;
#pragma unroll
        for (int mt = 0; mt < 2; mt++)
#pragma unroll
            for (int nt = 0; nt < 8; nt++) {
                float* p0 = Cw + (size_t)(mt * 16 + r) * ldC + nt * 8 + cq;
                float* p1 = p0 + 8 * (size_t)ldC;
                *(float2*)p0 = make_float2(acc[mt][nt][0] * oscale, acc[mt][nt][1] * oscale);
                *(float2*)p1 = make_float2(acc[mt][nt][2] * oscale, acc[mt][nt][3] * oscale);
            }
    } else if (OUT == 3) {
        // transposed per 4096-row batch: VT[b][n][m']; tiles never straddle batch
        const int gm0 = m0 + wm * 32;
        const int b = gm0 >> 12;
        __half* D = Chi + (size_t)b * AA * SS;
#pragma unroll
        for (int mt = 0; mt < 2; mt++)
#pragma unroll
            for (int nt = 0; nt < 8; nt++) {
                const int col = n0 + wn * 64 + nt * 8 + cq;
                const int ms0 = (gm0 + mt * 16 + r) & 4095;
                const int ms1 = ms0 + 8;
                D[(size_t)col * SS + ms0]       = __float2half_rn(acc[mt][nt][0] * oscale);
                D[(size_t)(col + 1) * SS + ms0] = __float2half_rn(acc[mt][nt][1] * oscale);
                D[(size_t)col * SS + ms1]       = __float2half_rn(acc[mt][nt][2] * oscale);
                D[(size_t)(col + 1) * SS + ms1] = __float2half_rn(acc[mt][nt][3] * oscale);
            }
    } else {
        const size_t off = (size_t)blockIdx.z * sC
                         + (size_t)(m0 + wm * 32) * ldC + n0 + wn * 64;
        __half* Hw = Chi + off;
        __half* Lw = Clo + off;
#pragma unroll
        for (int mt = 0; mt < 2; mt++)
#pragma unroll
            for (int nt = 0; nt < 8; nt++) {
                const size_t o0 = (size_t)(mt * 16 + r) * ldC + nt * 8 + cq;
                const size_t o1 = o0 + 8 * (size_t)ldC;
                float x0 = acc[mt][nt][0] * oscale, x1 = acc[mt][nt][1] * oscale;
                float x2 = acc[mt][nt][2] * oscale, x3 = acc[mt][nt][3] * oscale;
                __half h0 = __float2half_rn(x0), h1 = __float2half_rn(x1);
                __half h2 = __float2half_rn(x2), h3 = __float2half_rn(x3);
                *(__half2*)(Hw + o0) = __halves2half2(h0, h1);
                *(__half2*)(Hw + o1) = __halves2half2(h2, h3);
                __half l0 = __float2half_rn(x0 - __half2float(h0));
                __half l1 = __float2half_rn(x1 - __half2float(h1));
                __half l2 = __float2half_rn(x2 - __half2float(h2));
                __half l3 = __float2half_rn(x3 - __half2float(h3));
                *(__half2*)(Lw + o0) = __halves2half2(l0, l1);
                *(__half2*)(Lw + o1) = __halves2half2(l2, l3);
            }
    }
}

// ---------------------------------------------------------------------------
// fp32 -> scaled fp16 hi/lo split (elementwise)
// ---------------------------------------------------------------------------
__global__ __launch_bounds__(256)
void split_plain(const float* __restrict__ in, __half* __restrict__ hi,
                 __half* __restrict__ lo, size_t n, float scale)
{
    size_t i = ((size_t)blockIdx.x * 256 + threadIdx.x) * 4;
    if (i >= n) return;
    float4 x = *(const float4*)(in + i);
    x.x *= scale; x.y *= scale; x.z *= scale; x.w *= scale;
    __half h0 = __float2half_rn(x.x), h1 = __float2half_rn(x.y);
    __half h2 = __float2half_rn(x.z), h3 = __float2half_rn(x.w);
    __half l0 = __float2half_rn(x.x - __half2float(h0));
    __half l1 = __float2half_rn(x.y - __half2float(h1));
    __half l2 = __float2half_rn(x.z - __half2float(h2));
    __half l3 = __float2half_rn(x.w - __half2float(h3));
    *(__half2*)(hi + i)     = __halves2half2(h0, h1);
    *(__half2*)(hi + i + 2) = __halves2half2(h2, h3);
    *(__half2*)(lo + i)     = __halves2half2(l0, l1);
    *(__half2*)(lo + i + 2) = __halves2half2(l2, l3);
}

// Two-source variant: y selects {Wq, Wk}; writes into stacked dst at y*n
__global__ __launch_bounds__(256)
void split_plain2(const float* __restrict__ inA, const float* __restrict__ inB,
                  __half* __restrict__ hi, __half* __restrict__ lo,
                  size_t n, float scale)
{
    const float* in = blockIdx.y ? inB : inA;
    size_t base = (size_t)blockIdx.y * n;
    size_t i = ((size_t)blockIdx.x * 256 + threadIdx.x) * 4;
    if (i >= n) return;
    float4 x = *(const float4*)(in + i);
    x.x *= scale; x.y *= scale; x.z *= scale; x.w *= scale;
    __half h0 = __float2half_rn(x.x), h1 = __float2half_rn(x.y);
    __half h2 = __float2half_rn(x.z), h3 = __float2half_rn(x.w);
    __half l0 = __float2half_rn(x.x - __half2float(h0));
    __half l1 = __float2half_rn(x.y - __half2float(h1));
    __half l2 = __float2half_rn(x.z - __half2float(h2));
    __half l3 = __float2half_rn(x.w - __half2float(h3));
    *(__half2*)(hi + base + i)     = __halves2half2(h0, h1);
    *(__half2*)(hi + base + i + 2) = __halves2half2(h2, h3);
    *(__half2*)(lo + base + i)     = __halves2half2(l0, l1);
    *(__half2*)(lo + base + i + 2) = __halves2half2(l2, l3);
}

// Wt split-K reduce: sum 4 partials, scale, split to fp16 hi/lo
__global__ __launch_bounds__(256)
void wt_reduce(const float* __restrict__ part, __half* __restrict__ hi,
               __half* __restrict__ lo, size_t n, float scale)
{
    size_t i = ((size_t)blockIdx.x * 256 + threadIdx.x) * 4;
    if (i >= n) return;
    float4 a = *(const float4*)(part + i);
    float4 b = *(const float4*)(part + n + i);
    float4 c = *(const float4*)(part + 2 * n + i);
    float4 d = *(const float4*)(part + 3 * n + i);
    float x0 = (a.x + b.x + c.x + d.x) * scale;
    float x1 = (a.y + b.y + c.y + d.y) * scale;
    float x2 = (a.z + b.z + c.z + d.z) * scale;
    float x3 = (a.w + b.w + c.w + d.w) * scale;
    __half h0 = __float2half_rn(x0), h1 = __float2half_rn(x1);
    __half h2 = __float2half_rn(x2), h3 = __float2half_rn(x3);
    *(__half2*)(hi + i)     = __halves2half2(h0, h1);
    *(__half2*)(hi + i + 2) = __halves2half2(h2, h3);
    __half l0 = __float2half_rn(x0 - __half2float(h0));
    __half l1 = __float2half_rn(x1 - __half2float(h1));
    __half l2 = __float2half_rn(x2 - __half2float(h2));
    __half l3 = __float2half_rn(x3 - __half2float(h3));
    *(__half2*)(lo + i)     = __halves2half2(l0, l1);
    *(__half2*)(lo + i + 2) = __halves2half2(l2, l3);
}

// fp32 [R,C] -> transposed, scaled fp16 hi only [C,R]
__global__ __launch_bounds__(256)
void transpose_hi16(const float* __restrict__ in, __half* __restrict__ hiT,
                    int R, int C, float scale)
{
    __shared__ float t[32][33];
    const int r0 = blockIdx.y * 32, c0 = blockIdx.x * 32;
    const int tx = threadIdx.x & 31, ty = threadIdx.x >> 5;
#pragma unroll
    for (int i = ty; i < 32; i += 8)
        t[i][tx] = in[(size_t)(r0 + i) * C + c0 + tx];
    __syncthreads();
#pragma unroll
    for (int i = ty; i < 32; i += 8)
        hiT[(size_t)(c0 + i) * R + r0 + tx] = __float2half_rn(t[tx][i] * scale);
}

// ---------------------------------------------------------------------------
// Row softmax (4096 cols), warp-shuffle reductions, write fp16 (hi only)
// ---------------------------------------------------------------------------
__global__ __launch_bounds__(256)
void softmax_f16(const float* __restrict__ S, __half* __restrict__ Ph)
{
    const size_t row = blockIdx.x;
    const float* p = S + row * (size_t)SS;
    const int tid = threadIdx.x;
    const int lane = tid & 31, warp = tid >> 5;
    __shared__ float wred[8];

    float4 v[4];
    float m = -INFINITY;
#pragma unroll
    for (int i = 0; i < 4; i++) {
        v[i] = ((const float4*)p)[tid + i * 256];
        m = fmaxf(m, fmaxf(fmaxf(v[i].x, v[i].y), fmaxf(v[i].z, v[i].w)));
    }
#pragma unroll
    for (int o = 16; o > 0; o >>= 1)
        m = fmaxf(m, __shfl_xor_sync(0xffffffffu, m, o));
    if (lane == 0) wred[warp] = m;
    __syncthreads();
    {
        float t = wred[lane & 7];
#pragma unroll
        for (int o = 4; o > 0; o >>= 1)
            t = fmaxf(t, __shfl_xor_sync(0xffffffffu, t, o, 8));
        m = t;
    }

    float sum = 0.0f;
#pragma unroll
    for (int i = 0; i < 4; i++) {
        v[i].x = __expf(v[i].x - m);
        v[i].y = __expf(v[i].y - m);
        v[i].z = __expf(v[i].z - m);
        v[i].w = __expf(v[i].w - m);
        sum += v[i].x + v[i].y + v[i].z + v[i].w;
    }
#pragma unroll
    for (int o = 16; o > 0; o >>= 1)
        sum += __shfl_xor_sync(0xffffffffu, sum, o);
    __syncthreads();
    if (lane == 0) wred[warp] = sum;
    __syncthreads();
    {
        float t = wred[lane & 7];
#pragma unroll
        for (int o = 4; o > 0; o >>= 1)
            t += __shfl_xor_sync(0xffffffffu, t, o, 8);
        sum = t;
    }
    const float inv = 1.0f / sum;

#pragma unroll
    for (int i = 0; i < 4; i++) {
        size_t o = row * (size_t)SS + (size_t)(tid + i * 256) * 4;
        *(__half2*)(Ph + o)     = __halves2half2(__float2half_rn(v[i].x * inv),
                                                 __float2half_rn(v[i].y * inv));
        *(__half2*)(Ph + o + 2) = __halves2half2(__float2half_rn(v[i].z * inv),
                                                 __float2half_rn(v[i].w * inv));
    }
}

// ---------------------------------------------------------------------------
// kernel_launch — graph-capturable pipeline with capture-forked second stream
//   s0: splitX -> (wait Wt) Y -> scores -> softmax -> (wait Vproj) PV
//   s2: splitWqWk -> transposeWv -> Wt(split-K) -> reduce -> (wait splitX)
//       Vproj  [overlaps Y/scores on s0]
// ---------------------------------------------------------------------------
extern "C" void kernel_launch(void* const* d_in, const int* in_sizes, int n_in,
                              void* d_out, int out_size)
{
    const float* X  = (const float*)d_in[0];
    const float* Wq = (const float*)d_in[1];
    const float* Wk = (const float*)d_in[2];
    const float* Wv = (const float*)d_in[3];
    float* out = (float*)d_out;

    float *Sc, *WtP;
    __half *Xhi, *Xlo, *Wqkh, *Wqkl, *WvTh;
    __half *Wth, *Wtl, *Yhi, *Ylo, *Vthi, *Phi;
    cudaGetSymbolAddress((void**)&Sc, g_S);
    cudaGetSymbolAddress((void**)&WtP, g_Wt_part);
    cudaGetSymbolAddress((void**)&Xhi, g_Xhi);
    cudaGetSymbolAddress((void**)&Xlo, g_Xlo);
    cudaGetSymbolAddress((void**)&Wqkh, g_Wqk16h);
    cudaGetSymbolAddress((void**)&Wqkl, g_Wqk16l);
    cudaGetSymbolAddress((void**)&WvTh, g_WvTh);
    cudaGetSymbolAddress((void**)&Wth, g_Wth);
    cudaGetSymbolAddress((void**)&Wtl, g_Wtl);
    cudaGetSymbolAddress((void**)&Yhi, g_Yhi);
    cudaGetSymbolAddress((void**)&Ylo, g_Ylo);
    cudaGetSymbolAddress((void**)&Vthi, g_Vthi);
    cudaGetSymbolAddress((void**)&Phi, g_Phi);

    const size_t WSZ = (size_t)DD * AA;
    __half* Wq16h = Wqkh;            // y=0 slot
    __half* Wq16l = Wqkl;
    __half* Wk16h = Wqkh + WSZ;      // y=1 slot
    __half* Wk16l = Wqkl + WSZ;

    const int SMEM_NT3 = 2 * 4 * TILE_T;   // 81920
    const int SMEM_NT1 = 2 * 2 * TILE_T;   // 40960
    cudaFuncSetAttribute(gemm_mma<3,0>, cudaFuncAttributeMaxDynamicSharedMemorySize, SMEM_NT3);
    cudaFuncSetAttribute(gemm_mma<3,1>, cudaFuncAttributeMaxDynamicSharedMemorySize, SMEM_NT3);
    cudaFuncSetAttribute(gemm_mma<1,0>, cudaFuncAttributeMaxDynamicSharedMemorySize, SMEM_NT1);
    cudaFuncSetAttribute(gemm_mma<1,3>, cudaFuncAttributeMaxDynamicSharedMemorySize, SMEM_NT1);

    const float INV16 = 1.0f / 16.0f;

    // fork a second stream off the capturing (default) stream
    cudaStream_t s2;
    cudaStreamCreateWithFlags(&s2, cudaStreamNonBlocking);
    cudaEvent_t eF, eX, eW, eV;
    cudaEventCreateWithFlags(&eF, cudaEventDisableTiming);
    cudaEventCreateWithFlags(&eX, cudaEventDisableTiming);
    cudaEventCreateWithFlags(&eW, cudaEventDisableTiming);
    cudaEventCreateWithFlags(&eV, cudaEventDisableTiming);

    cudaEventRecord(eF, 0);
    cudaStreamWaitEvent(s2, eF, 0);

    // ---- s2: weight pipeline ----
    {
        dim3 g((unsigned)(WSZ / 1024), 2, 1);
        split_plain2<<<g, 256, 0, s2>>>(Wq, Wk, Wqkh, Wqkl, WSZ, 16.0f);
    }
    {
        dim3 g(AA / 32, DD / 32, 1);
        transpose_hi16<<<g, 256, 0, s2>>>(Wv, WvTh, DD, AA, 16.0f);
    }
    {
        dim3 g(DD / 128, DD / 128, 4);
        gemm_mma<3,0><<<g, 256, SMEM_NT3, s2>>>(Wk16h, Wk16l, Wq16h, Wq16l,
                                                WtP, nullptr, nullptr,
                                                AA / 4, AA, DD,
                                                AA / 4, AA / 4, (long long)DD * DD, 1.0f);
        wt_reduce<<<((size_t)DD * DD) / 1024, 256, 0, s2>>>(WtP, Wth, Wtl,
                                                            (size_t)DD * DD, INV16);
    }
    cudaEventRecord(eW, s2);

    // ---- s0: X split ----
    split_plain<<<(MTOT * (size_t)DD) / 1024, 256>>>(X, Xhi, Xlo, (size_t)MTOT * DD, 1.0f);
    cudaEventRecord(eX, 0);

    // ---- s2: V projection (needs X split + WvT), runs parallel to Y/scores ----
    cudaStreamWaitEvent(s2, eX, 0);
    {
        dim3 g(AA / 128, MTOT / 128, 1);
        gemm_mma<1,3><<<g, 256, SMEM_NT1, s2>>>(Xhi, nullptr, WvTh, nullptr,
                                                nullptr, Vthi, nullptr,
                                                DD, DD, 0, 0, 0, 0, INV16);
    }
    cudaEventRecord(eV, s2);

    // ---- s0: Y = X @ Wt (needs Wt) ----
    cudaStreamWaitEvent(0, eW, 0);
    {
        dim3 g(DD / 128, MTOT / 128, 1);
        gemm_mma<3,1><<<g, 256, SMEM_NT3>>>(Xhi, Xlo, Wth, Wtl,
                                            nullptr, Yhi, Ylo,
                                            DD, DD, DD, 0, 0, 0, INV16);
    }

    // ---- s0: scores = Y @ X^T per batch ----
    {
        dim3 g(SS / 128, SS / 128, BB);
        gemm_mma<3,0><<<g, 256, SMEM_NT3>>>(Yhi, Ylo, Xhi, Xlo, Sc, nullptr, nullptr,
                                            DD, DD, SS,
                                            (long long)SS * DD, (long long)SS * DD,
                                            (long long)SS * SS, 1.0f);
    }

    // ---- s0: softmax -> fp16 P ----
    softmax_f16<<<BB * SS, 256>>>(Sc, Phi);

    // ---- s0: join V, then PV ----
    cudaStreamWaitEvent(0, eV, 0);
    {
        dim3 g(AA / 128, SS / 128, BB);
        gemm_mma<1,0><<<g, 256, SMEM_NT1>>>(Phi, nullptr, Vthi, nullptr,
                                            out, nullptr, nullptr,
                                            SS, SS, AA,
                                            (long long)SS * SS, (long long)AA * SS,
                                            (long long)SS * AA, 1.0f);
    }

    cudaEventDestroy(eF);
    cudaEventDestroy(eX);
    cudaEventDestroy(eW);
    cudaEventDestroy(eV);
    cudaStreamDestroy(s2);
}